// round 12
// baseline (speedup 1.0000x reference)
#include <cuda_runtime.h>
#include <cstdint>

// SpatialTransformer bilinear flow warp — R8 skeleton + paired 64-bit gathers.
// src:  [B,H,W,1] f32,  flow: [B,H,W,2] f32,  out: [B,H,W,1] f32
// B=32, H=768, W=768.
//
// R11 analysis: kernel is L1tex sector-bandwidth bound. va/vb (x0, x0+1)
// share a 32B sector ~87% of the time but two LDG.32s pay the sector twice.
// Fix: aligned float2 pair-loads at e = x0 & ~1 and e+2, parity-select.
//   - always 8B aligned (e even, rows 8B aligned since W=768)
//   - memory safe: e+3 <= row end +2, stays inside image b (only read,
//     value discarded when x0 even)
//   - bit-identical results (same source values, same weights/FMAs)
// Layout unchanged: 32x16 tile / 128-thr block, warp = 32 consecutive x,
// 4-row strip per thread. Plain __ldg/stores (R11 cache hints reverted).

#define BB 32
#define HH 768
#define WW 768
#define HW (HH * WW)

__global__ __launch_bounds__(128) void warp_kernel(
    const float* __restrict__ src,
    const float* __restrict__ flow,
    float* __restrict__ out)
{
    const int tx = threadIdx.x;
    const int xg = blockIdx.x * 32 + (tx & 31);       // global x
    const int yb = blockIdx.y * 16 + (tx >> 5) * 4;   // first of 4 rows
    const int b  = blockIdx.z;

    const float* img = src + b * HW;
    const float  xgf = (float)xg;

    #pragma unroll
    for (int r = 0; r < 4; r++) {
        const int y   = yb + r;
        const int pix = (b * HH + y) * WW + xg;

        const float2 f = *reinterpret_cast<const float2*>(flow + (size_t)pix * 2);

        const float gx = xgf + f.x;
        const float gy = (float)y + f.y;

        const float x0f = floorf(gx);
        const float y0f = floorf(gy);
        const float x1f = x0f + 1.0f;
        const float y1f = y0f + 1.0f;

        // weights from UNCLIPPED corners — exact reference formulation
        const float dx1 = x1f - gx;
        const float dx0 = gx - x0f;
        const float dy1 = y1f - gy;
        const float dy0 = gy - y0f;

        const float wa = dx1 * dy1;
        const float wb = dx0 * dy1;
        const float wc = dx1 * dy0;
        const float wd = dx0 * dy0;

        const int ix0 = (int)x0f;
        const int iy0 = (int)y0f;

        float va, vb, vc, vd;
        // fast iff ix0 in [0, W-2] and iy0 in [0, H-2]: clamps are identity
        if (((unsigned)ix0 < (WW - 1)) & ((unsigned)iy0 < (HH - 1))) {
            const int  e   = ix0 & ~1;         // even, 8B-aligned column
            const bool odd = (ix0 & 1);
            const float* p0 = img + iy0 * WW + e;

            const float2 lo0 = __ldg(reinterpret_cast<const float2*>(p0));
            const float2 hi0 = __ldg(reinterpret_cast<const float2*>(p0 + 2));
            const float2 lo1 = __ldg(reinterpret_cast<const float2*>(p0 + WW));
            const float2 hi1 = __ldg(reinterpret_cast<const float2*>(p0 + WW + 2));

            va = odd ? lo0.y : lo0.x;
            vb = odd ? hi0.x : lo0.y;
            vc = odd ? lo1.y : lo1.x;
            vd = odd ? hi1.x : lo1.y;
        } else {
            // exact reference slow path (clamped indices)
            const int xi0 = (int)fminf(fmaxf(x0f, 0.0f), (float)(WW - 1));
            const int xi1 = (int)fminf(fmaxf(x1f, 0.0f), (float)(WW - 1));
            const int yi0 = (int)fminf(fmaxf(y0f, 0.0f), (float)(HH - 1));
            const int yi1 = (int)fminf(fmaxf(y1f, 0.0f), (float)(HH - 1));
            const int g0 = yi0 * WW;
            const int g1 = yi1 * WW;
            va = __ldg(img + g0 + xi0);
            vb = __ldg(img + g0 + xi1);
            vc = __ldg(img + g1 + xi0);
            vd = __ldg(img + g1 + xi1);
        }

        out[pix] = wa * va + wb * vb + wc * vc + wd * vd;
    }
}

extern "C" void kernel_launch(void* const* d_in, const int* in_sizes, int n_in,
                              void* d_out, int out_size)
{
    const float* src  = (const float*)d_in[0];
    const float* flow = (const float*)d_in[1];
    float* out = (float*)d_out;

    dim3 grid(WW / 32, HH / 16, BB);   // (24, 48, 32)
    warp_kernel<<<grid, 128>>>(src, flow, out);
}